// round 13
// baseline (speedup 1.0000x reference)
#include <cuda_runtime.h>
#include <cuda_bf16.h>
#include <math.h>
#include <cstdint>

#define BN 8192
#define DD 128
#define NT (BN/128)                 // 64 h-blocks
#define NPAIRU 1056                 // paired-j triangular units
#define FARV (-0.00995033085316808285f)

#define RS   272                    // padded smem row stride (bytes)
#define RSU4 17
#define TILE128 (128*RS)            // 34816 B
#define TILE64  (64*RS)

// Device state. g_h / g_wt are PLAIN row-major bf16 (256B rows); padding is
// applied when staging into smem (dst uint4 index = e + (e>>4)).
__device__ __nv_bfloat16 g_h[BN*DD];
__device__ __nv_bfloat16 g_wt[3][DD*DD];   // row n = column n of W
__device__ float  g_sq[BN];
__device__ double g_loss;
__device__ double g_hsum;
__device__ unsigned g_ticket;

// ---------------- warp-MMA helpers (plain sm_80+ PTX) ----------------------
__device__ __forceinline__ void ldm_x4(uint32_t& r0, uint32_t& r1,
                                       uint32_t& r2, uint32_t& r3, uint32_t addr) {
    asm volatile("ldmatrix.sync.aligned.m8n8.x4.shared.b16 {%0,%1,%2,%3}, [%4];"
                 : "=r"(r0), "=r"(r1), "=r"(r2), "=r"(r3) : "r"(addr));
}
__device__ __forceinline__ void mma_bf16(float* d, const uint32_t* a, const uint32_t* b) {
    asm volatile("mma.sync.aligned.m16n8k16.row.col.f32.bf16.bf16.f32 "
                 "{%0,%1,%2,%3}, {%4,%5,%6,%7}, {%8,%9}, {%0,%1,%2,%3};"
                 : "+f"(d[0]), "+f"(d[1]), "+f"(d[2]), "+f"(d[3])
                 : "r"(a[0]), "r"(a[1]), "r"(a[2]), "r"(a[3]), "r"(b[0]), "r"(b[1]));
}
__device__ __forceinline__ uint32_t smem_to_u32(const void* p) {
    uint32_t a;
    asm("{ .reg .u64 t; cvta.to.shared.u64 t, %1; cvt.u32.u64 %0, t; }" : "=r"(a) : "l"(p));
    return a;
}

// ---------------------------------------------------------------------------
// Prep (48 CTAs): CTA (w, s) transposes k-slice [8s, 8s+8) of W_w.
// ---------------------------------------------------------------------------
__global__ void __launch_bounds__(256)
k_prep(const float* __restrict__ W1, const float* __restrict__ W2,
       const float* __restrict__ W3) {
    __shared__ float stage[8*DD];      // 4KB
    int tid = threadIdx.x;
    int w = blockIdx.x >> 4, s = blockIdx.x & 15;
    const float* W = (w == 0) ? W1 : (w == 1) ? W2 : W3;
    if (tid < 256) ((float4*)stage)[tid] = ((const float4*)W)[s*256 + tid];
    __syncthreads();
    if (tid < 128) {
        int n = tid;
        uint32_t pk[4];
        #pragma unroll
        for (int p = 0; p < 4; p++) {
            float lo = stage[(2*p    ) * DD + n];
            float hi = stage[(2*p + 1) * DD + n];
            __nv_bfloat162 h2 = __float22bfloat162_rn(make_float2(lo, hi));
            pk[p] = *(const uint32_t*)&h2;
        }
        ((uint4*)g_wt[w])[n*16 + s] = make_uint4(pk[0], pk[1], pk[2], pk[3]);
    }
    if (blockIdx.x == 0 && tid == 0) { g_loss = 0.0; g_hsum = 0.0; g_ticket = 0u; }
}

// ---------------------------------------------------------------------------
// Tensor-core MLP (unchanged from R12): 128 CTAs x 64 rows, 3 CTAs/SM.
// ---------------------------------------------------------------------------
#define MLP_A 1024
#define MLP_B (1024 + TILE64)
#define MLP_W (1024 + 2*TILE64)
#define MLP_SMEM (1024 + 2*TILE64 + TILE128)

__device__ __forceinline__ void mlp_mma(const char* smc, int aOff, float acc[2][4][4],
                                        int lane, int wr, int wc) {
    uint32_t aB = smem_to_u32(smc + aOff);
    uint32_t wB = smem_to_u32(smc + MLP_W);
    #pragma unroll
    for (int mt = 0; mt < 2; mt++)
        #pragma unroll
        for (int nt = 0; nt < 4; nt++)
            #pragma unroll
            for (int k = 0; k < 4; k++) acc[mt][nt][k] = 0.0f;

    int bg = lane >> 3;
    uint32_t aA0 = aB + (uint32_t)(wr*32 + (lane & 15))*RS + (uint32_t)(lane >> 4)*16;
    uint32_t bA0 = wB + (uint32_t)(wc*32 + ((bg >> 1) << 3) + (lane & 7))*RS
                 + (uint32_t)(bg & 1)*16;

    #pragma unroll
    for (int ks = 0; ks < 8; ks++) {
        uint32_t a[2][4];
        ldm_x4(a[0][0], a[0][1], a[0][2], a[0][3], aA0 + ks*32);
        ldm_x4(a[1][0], a[1][1], a[1][2], a[1][3], aA0 + 16*RS + ks*32);
        uint32_t bfr[4][2];
        {
            uint32_t r0, r1, r2, r3;
            ldm_x4(r0, r1, r2, r3, bA0 + ks*32);
            bfr[0][0] = r0; bfr[0][1] = r1; bfr[1][0] = r2; bfr[1][1] = r3;
            ldm_x4(r0, r1, r2, r3, bA0 + 16*RS + ks*32);
            bfr[2][0] = r0; bfr[2][1] = r1; bfr[3][0] = r2; bfr[3][1] = r3;
        }
        #pragma unroll
        for (int mt = 0; mt < 2; mt++)
            #pragma unroll
            for (int nt = 0; nt < 4; nt++)
                mma_bf16(acc[mt][nt], a[mt], bfr[nt]);
    }
}

template<bool RELU, bool LAST>
__device__ __forceinline__ void mlp_store(char* smc, int outOff, float acc[2][4][4],
                                          int lane, int wr, int wc) {
    const float* biasf = (const float*)smc;
    float* sq_sm = (float*)(smc + 512);
    int r8 = lane >> 2, c2 = (lane & 3) << 1;
    #pragma unroll
    for (int mt = 0; mt < 2; mt++) {
        float srow[2] = {0.0f, 0.0f};
        #pragma unroll
        for (int nt = 0; nt < 4; nt++) {
            int col = wc*32 + nt*8 + c2;
            float b0 = biasf[col], b1 = biasf[col + 1];
            #pragma unroll
            for (int h8 = 0; h8 < 2; h8++) {
                float f0 = acc[mt][nt][h8*2]     + b0;
                float f1 = acc[mt][nt][h8*2 + 1] + b1;
                if (RELU) { f0 = fmaxf(f0, 0.0f); f1 = fmaxf(f1, 0.0f); }
                __nv_bfloat162 p = __float22bfloat162_rn(make_float2(f0, f1));
                uint32_t pk = *(const uint32_t*)&p;
                int r = wr*32 + mt*16 + h8*8 + r8;
                int chunk = wc*4 + nt;
                uint32_t off = (uint32_t)outOff + (uint32_t)r*RS
                             + (uint32_t)chunk*16 + (uint32_t)c2*2;
                *(uint32_t*)(smc + off) = pk;
                if (LAST) {
                    float2 fb = __bfloat1622float2(p);
                    srow[h8] += fb.x*fb.x + fb.y*fb.y;
                }
            }
        }
        if (LAST) {
            #pragma unroll
            for (int h8 = 0; h8 < 2; h8++) {
                float s = srow[h8];
                s += __shfl_xor_sync(0xffffffffu, s, 1);
                s += __shfl_xor_sync(0xffffffffu, s, 2);
                if ((lane & 3) == 0)
                    atomicAdd(&sq_sm[wr*32 + mt*16 + h8*8 + r8], s);
            }
        }
    }
}

__global__ void __launch_bounds__(256, 3)
k_mlp(const float* __restrict__ X, const float* __restrict__ b1,
      const float* __restrict__ b2, const float* __restrict__ b3) {
    extern __shared__ char smc[];
    float* biasf = (float*)smc;
    float* sq_sm = (float*)(smc + 512);
    float* red   = (float*)(smc + 768);

    int tid = threadIdx.x, wid = tid >> 5, lane = tid & 31;
    int wr = wid & 1, wc = wid >> 1;
    int r0 = blockIdx.x * 64;

    uint4* Au4 = (uint4*)(smc + MLP_A);
    uint4* Wu4 = (uint4*)(smc + MLP_W);

    const float4* src = (const float4*)(X + r0*DD);
    for (int e = tid; e < 1024; e += 256) {
        int row = e >> 4, c = e & 15;
        float4 v0 = src[row*32 + c*2];
        float4 v1 = src[row*32 + c*2 + 1];
        __nv_bfloat162 p0 = __float22bfloat162_rn(make_float2(v0.x, v0.y));
        __nv_bfloat162 p1 = __float22bfloat162_rn(make_float2(v0.z, v0.w));
        __nv_bfloat162 p2 = __float22bfloat162_rn(make_float2(v1.x, v1.y));
        __nv_bfloat162 p3 = __float22bfloat162_rn(make_float2(v1.z, v1.w));
        Au4[row*RSU4 + c] = make_uint4(*(const uint32_t*)&p0, *(const uint32_t*)&p1,
                                       *(const uint32_t*)&p2, *(const uint32_t*)&p3);
    }
    for (int e = tid; e < 2048; e += 256) Wu4[e + (e >> 4)] = ((const uint4*)g_wt[0])[e];
    if (tid < DD) biasf[tid] = b1[tid];
    if (tid < 64) sq_sm[tid] = 0.0f;
    __syncthreads();

    float acc[2][4][4];

    mlp_mma(smc, MLP_A, acc, lane, wr, wc);
    __syncthreads();
    mlp_store<true, false>(smc, MLP_B, acc, lane, wr, wc);
    for (int e = tid; e < 2048; e += 256) Wu4[e + (e >> 4)] = ((const uint4*)g_wt[1])[e];
    __syncthreads();
    if (tid < DD) biasf[tid] = b2[tid];
    __syncthreads();

    mlp_mma(smc, MLP_B, acc, lane, wr, wc);
    __syncthreads();
    mlp_store<true, false>(smc, MLP_A, acc, lane, wr, wc);
    for (int e = tid; e < 2048; e += 256) Wu4[e + (e >> 4)] = ((const uint4*)g_wt[2])[e];
    __syncthreads();
    if (tid < DD) biasf[tid] = b3[tid];
    __syncthreads();

    mlp_mma(smc, MLP_A, acc, lane, wr, wc);
    __syncthreads();
    mlp_store<false, true>(smc, MLP_B, acc, lane, wr, wc);
    __syncthreads();

    for (int e = tid; e < 1024; e += 256) {
        int row = e >> 4;
        ((uint4*)g_h)[(r0 + row)*16 + (e & 15)] = ((uint4*)(smc + MLP_B))[e + row];
    }
    if (tid < 64) {
        float sv = sq_sm[tid];
        g_sq[r0 + tid] = sv;
        sv += __shfl_xor_sync(0xffffffffu, sv, 16);
        sv += __shfl_xor_sync(0xffffffffu, sv, 8);
        sv += __shfl_xor_sync(0xffffffffu, sv, 4);
        sv += __shfl_xor_sync(0xffffffffu, sv, 2);
        sv += __shfl_xor_sync(0xffffffffu, sv, 1);
        if (lane == 0) red[wid] = sv;
    }
    __syncthreads();
    if (tid == 0) atomicAdd(&g_hsum, (double)(red[0] + red[1]));
}

// ---------------------------------------------------------------------------
// Pairwise: 512-thread CTAs, each computes a 128x256 mega-tile: Hi block bi
// against j-blocks (bj0, bj0+1). 1056 units. 16 warps in a 4x4 grid:
// wr = wid&3 (32 rows), wc = wid>>2 (64 of 256 cols). Per-half loss weights
// (1 diag / 2 off-diag / 0 absent-edge) replace CTA-level doubling.
// smem: header 4KB | Hi(128r) | Hj(256r) = 108544 B, 2 CTAs/SM.
// ---------------------------------------------------------------------------
#define P_SQI 64
#define P_SQJ 576
#define P_YI  1600
#define P_YJ  2112
#define HI_OFF 4096
#define HJ_OFF (4096 + TILE128)
#define PAIR_SMEM (4096 + 3*TILE128)

__global__ void __launch_bounds__(512, 2)
k_pair(const int* __restrict__ y, float* __restrict__ out) {
    extern __shared__ char smc[];
    float* redf = (float*)smc;          // 16 floats
    float* sqi  = (float*)(smc + P_SQI);
    float* sqj  = (float*)(smc + P_SQJ);
    int*   yi   = (int*)(smc + P_YI);
    int*   yj   = (int*)(smc + P_YJ);

    int tid = threadIdx.x, wid = tid >> 5, lane = tid & 31;
    int wr = wid & 3, wc = wid >> 2;

    // unit -> (bi, bj0, bj0+1)
    int rem = blockIdx.x, bi = 0;
    while (true) {
        int np = (65 - bi) >> 1;
        if (rem < np) break;
        rem -= np; bi++;
    }
    int bj0 = bi + 2*rem;
    bool has2 = (bj0 + 1 < NT);
    int bj1 = has2 ? bj0 + 1 : bj0;
    float w0f = (bj0 == bi) ? 1.0f : 2.0f;
    float w1f = has2 ? 2.0f : 0.0f;

    // tile loads: plain g_h rows -> padded smem
    const uint4* gh = (const uint4*)g_h;
    uint4* Hi = (uint4*)(smc + HI_OFF);
    uint4* Hj = (uint4*)(smc + HJ_OFF);
    for (int e = tid; e < 2048; e += 512)
        Hi[e + (e >> 4)] = gh[bi*2048 + e];
    for (int e = tid; e < 4096; e += 512) {
        int blk = e >> 11;
        Hj[e + (e >> 4)] = gh[(blk ? bj1 : bj0)*2048 + (e & 2047)];
    }
    if (tid < 256) {
        int jb = tid >> 7, src = (jb ? bj1 : bj0)*128 + (tid & 127);
        sqj[tid] = g_sq[src];
        yj[tid]  = y[src];
    } else if (tid < 384) {
        int i = tid - 256;
        sqi[i] = g_sq[bi*128 + i];
        yi[i]  = y[bi*128 + i];
    }
    __syncthreads();

    uint32_t hiB = smem_to_u32(smc + HI_OFF);
    uint32_t hjB = smem_to_u32(smc + HJ_OFF);

    int bg = lane >> 3;
    uint32_t aA0 = hiB + (uint32_t)(wr*32 + (lane & 15))*RS + (uint32_t)(lane >> 4)*16;
    uint32_t bBase = hjB + (uint32_t)(((bg >> 1) << 3) + (lane & 7))*RS
                   + (uint32_t)(bg & 1)*16;

    int r8 = lane >> 2, c2 = (lane & 3) << 1;
    float si[2][2]; int li[2][2];
    #pragma unroll
    for (int mt = 0; mt < 2; mt++)
        #pragma unroll
        for (int h = 0; h < 2; h++) {
            int row = wr*32 + mt*16 + h*8 + r8;
            si[mt][h] = sqi[row];
            li[mt][h] = yi[row];
        }

    float lsum = 0.0f;

    #pragma unroll 1
    for (int p = 0; p < 2; p++) {
        int gc = wc*64 + p*32;
        uint32_t bA0 = bBase + (uint32_t)gc*RS;
        float wgt = (gc >> 7) ? w1f : w0f;

        float acc[2][4][4];
        #pragma unroll
        for (int mt = 0; mt < 2; mt++)
            #pragma unroll
            for (int nt = 0; nt < 4; nt++)
                #pragma unroll
                for (int k = 0; k < 4; k++) acc[mt][nt][k] = 0.0f;

        #pragma unroll
        for (int ks = 0; ks < 8; ks++) {
            uint32_t a[2][4];
            ldm_x4(a[0][0], a[0][1], a[0][2], a[0][3], aA0 + ks*32);
            ldm_x4(a[1][0], a[1][1], a[1][2], a[1][3], aA0 + 16*RS + ks*32);
            uint32_t bfr[4][2];
            {
                uint32_t r0, r1, r2, r3;
                ldm_x4(r0, r1, r2, r3, bA0 + ks*32);
                bfr[0][0] = r0; bfr[0][1] = r1; bfr[1][0] = r2; bfr[1][1] = r3;
                ldm_x4(r0, r1, r2, r3, bA0 + 16*RS + ks*32);
                bfr[2][0] = r0; bfr[2][1] = r1; bfr[3][0] = r2; bfr[3][1] = r3;
            }
            #pragma unroll
            for (int mt = 0; mt < 2; mt++)
                #pragma unroll
                for (int nt = 0; nt < 4; nt++)
                    mma_bf16(acc[mt][nt], a[mt], bfr[nt]);
        }

        // epilogue for this 32-col half
        float hs = 0.0f;
        int rare = 0;
        #pragma unroll
        for (int nt = 0; nt < 4; nt++) {
            #pragma unroll
            for (int q = 0; q < 2; q++) {
                int col = gc + nt*8 + c2 + q;
                float sjv = sqj[col];
                int   ljv = yj[col];
                #pragma unroll
                for (int mt = 0; mt < 2; mt++)
                    #pragma unroll
                    for (int h = 0; h < 2; h++) {
                        float d = acc[mt][nt][h*2 + q];
                        float dist = fmaf(-2.0f, d, si[mt][h] + sjv);
                        bool  eq = (li[mt][h] == ljv);
                        hs += eq ? dist : FARV;
                        rare |= (!eq && dist < 18.0f);
                    }
            }
        }
        if (__any_sync(0xffffffffu, rare)) {
            #pragma unroll
            for (int nt = 0; nt < 4; nt++)
                #pragma unroll
                for (int q = 0; q < 2; q++) {
                    int col = gc + nt*8 + c2 + q;
                    float sjv = sqj[col];
                    int   ljv = yj[col];
                    #pragma unroll
                    for (int mt = 0; mt < 2; mt++)
                        #pragma unroll
                        for (int h = 0; h < 2; h++) {
                            float d = acc[mt][nt][h*2 + q];
                            float dist = fmaxf(fmaf(-2.0f, d, si[mt][h] + sjv), 0.0f);
                            bool  eq = (li[mt][h] == ljv);
                            if (!eq && dist < 18.0f)
                                hs += (-logf(1.01f - expf(-dist))) - FARV;
                        }
                }
        }
        lsum += wgt * hs;
    }

    lsum += __shfl_xor_sync(0xffffffffu, lsum, 1);
    lsum += __shfl_xor_sync(0xffffffffu, lsum, 2);
    lsum += __shfl_xor_sync(0xffffffffu, lsum, 4);
    lsum += __shfl_xor_sync(0xffffffffu, lsum, 8);
    lsum += __shfl_xor_sync(0xffffffffu, lsum, 16);
    if (lane == 0) redf[wid] = lsum;
    __syncthreads();
    if (tid == 0) {
        double tot = 0.0;
        for (int w = 0; w < 16; w++) tot += (double)redf[w];
        atomicAdd(&g_loss, tot);
        __threadfence();
        unsigned tk = atomicAdd(&g_ticket, 1u);
        if (tk == NPAIRU - 1) {
            __threadfence();
            double lt = atomicAdd(&g_loss, 0.0);
            double hs2 = atomicAdd(&g_hsum, 0.0);
            double loss = lt / ((double)BN * (double)BN);
            loss += 0.01 * (hs2 / ((double)BN * (double)DD));
            out[0] = (float)loss;
        }
    }
}

// ---------------------------------------------------------------------------

extern "C" void kernel_launch(void* const* d_in, const int* in_sizes, int n_in,
                              void* d_out, int out_size) {
    (void)in_sizes; (void)n_in; (void)out_size;
    const float* X  = (const float*)d_in[0];
    const float* W1 = (const float*)d_in[1];
    const float* b1 = (const float*)d_in[2];
    const float* W2 = (const float*)d_in[3];
    const float* b2 = (const float*)d_in[4];
    const float* W3 = (const float*)d_in[5];
    const float* b3 = (const float*)d_in[6];
    const int*   y  = (const int*)d_in[7];

    cudaFuncSetAttribute(k_mlp,  cudaFuncAttributeMaxDynamicSharedMemorySize, MLP_SMEM);
    cudaFuncSetAttribute(k_pair, cudaFuncAttributeMaxDynamicSharedMemorySize, PAIR_SMEM);

    k_prep<<<48, 256>>>(W1, W2, W3);
    k_mlp<<<BN/64, 256, MLP_SMEM>>>(X, b1, b2, b3);
    k_pair<<<NPAIRU, 512, PAIR_SMEM>>>(y, (float*)d_out);
}

// round 14
// speedup vs baseline: 1.4048x; 1.4048x over previous
#include <cuda_runtime.h>
#include <cuda_bf16.h>
#include <math.h>
#include <cstdint>

#define BN 8192
#define DD 128
#define NT (BN/128)                 // 64 h-blocks
#define NPAIRU 1056                 // paired-j triangular units
#define FARV (-0.00995033085316808285f)

#define RS   272                    // padded smem row stride (bytes)
#define RSU4 17
#define TILE128 (128*RS)            // 34816 B
#define TILE64  (64*RS)

// Device state. g_h / g_wt are PLAIN row-major bf16 (256B rows); padding is
// applied when staging into smem (dst uint4 index = e + (e>>4)).
__device__ __nv_bfloat16 g_h[BN*DD];
__device__ __nv_bfloat16 g_wt[3][DD*DD];   // row n = column n of W
__device__ float  g_sq[BN];
__device__ double g_loss;
__device__ double g_hsum;
__device__ unsigned g_ticket;

// ---------------- warp-MMA helpers (plain sm_80+ PTX) ----------------------
__device__ __forceinline__ void ldm_x4(uint32_t& r0, uint32_t& r1,
                                       uint32_t& r2, uint32_t& r3, uint32_t addr) {
    asm volatile("ldmatrix.sync.aligned.m8n8.x4.shared.b16 {%0,%1,%2,%3}, [%4];"
                 : "=r"(r0), "=r"(r1), "=r"(r2), "=r"(r3) : "r"(addr));
}
__device__ __forceinline__ void mma_bf16(float* d, const uint32_t* a, const uint32_t* b) {
    asm volatile("mma.sync.aligned.m16n8k16.row.col.f32.bf16.bf16.f32 "
                 "{%0,%1,%2,%3}, {%4,%5,%6,%7}, {%8,%9}, {%0,%1,%2,%3};"
                 : "+f"(d[0]), "+f"(d[1]), "+f"(d[2]), "+f"(d[3])
                 : "r"(a[0]), "r"(a[1]), "r"(a[2]), "r"(a[3]), "r"(b[0]), "r"(b[1]));
}
__device__ __forceinline__ uint32_t smem_to_u32(const void* p) {
    uint32_t a;
    asm("{ .reg .u64 t; cvta.to.shared.u64 t, %1; cvt.u32.u64 %0, t; }" : "=r"(a) : "l"(p));
    return a;
}

// ---------------------------------------------------------------------------
// Prep (48 CTAs): CTA (w, s) transposes k-slice [8s, 8s+8) of W_w.
// ---------------------------------------------------------------------------
__global__ void __launch_bounds__(256)
k_prep(const float* __restrict__ W1, const float* __restrict__ W2,
       const float* __restrict__ W3) {
    __shared__ float stage[8*DD];      // 4KB
    int tid = threadIdx.x;
    int w = blockIdx.x >> 4, s = blockIdx.x & 15;
    const float* W = (w == 0) ? W1 : (w == 1) ? W2 : W3;
    if (tid < 256) ((float4*)stage)[tid] = ((const float4*)W)[s*256 + tid];
    __syncthreads();
    if (tid < 128) {
        int n = tid;
        uint32_t pk[4];
        #pragma unroll
        for (int p = 0; p < 4; p++) {
            float lo = stage[(2*p    ) * DD + n];
            float hi = stage[(2*p + 1) * DD + n];
            __nv_bfloat162 h2 = __float22bfloat162_rn(make_float2(lo, hi));
            pk[p] = *(const uint32_t*)&h2;
        }
        ((uint4*)g_wt[w])[n*16 + s] = make_uint4(pk[0], pk[1], pk[2], pk[3]);
    }
    if (blockIdx.x == 0 && tid == 0) { g_loss = 0.0; g_hsum = 0.0; g_ticket = 0u; }
}

// ---------------------------------------------------------------------------
// Tensor-core MLP (unchanged from R12): 128 CTAs x 64 rows, 3 CTAs/SM.
// ---------------------------------------------------------------------------
#define MLP_A 1024
#define MLP_B (1024 + TILE64)
#define MLP_W (1024 + 2*TILE64)
#define MLP_SMEM (1024 + 2*TILE64 + TILE128)

__device__ __forceinline__ void mlp_mma(const char* smc, int aOff, float acc[2][4][4],
                                        int lane, int wr, int wc) {
    uint32_t aB = smem_to_u32(smc + aOff);
    uint32_t wB = smem_to_u32(smc + MLP_W);
    #pragma unroll
    for (int mt = 0; mt < 2; mt++)
        #pragma unroll
        for (int nt = 0; nt < 4; nt++)
            #pragma unroll
            for (int k = 0; k < 4; k++) acc[mt][nt][k] = 0.0f;

    int bg = lane >> 3;
    uint32_t aA0 = aB + (uint32_t)(wr*32 + (lane & 15))*RS + (uint32_t)(lane >> 4)*16;
    uint32_t bA0 = wB + (uint32_t)(wc*32 + ((bg >> 1) << 3) + (lane & 7))*RS
                 + (uint32_t)(bg & 1)*16;

    #pragma unroll
    for (int ks = 0; ks < 8; ks++) {
        uint32_t a[2][4];
        ldm_x4(a[0][0], a[0][1], a[0][2], a[0][3], aA0 + ks*32);
        ldm_x4(a[1][0], a[1][1], a[1][2], a[1][3], aA0 + 16*RS + ks*32);
        uint32_t bfr[4][2];
        {
            uint32_t r0, r1, r2, r3;
            ldm_x4(r0, r1, r2, r3, bA0 + ks*32);
            bfr[0][0] = r0; bfr[0][1] = r1; bfr[1][0] = r2; bfr[1][1] = r3;
            ldm_x4(r0, r1, r2, r3, bA0 + 16*RS + ks*32);
            bfr[2][0] = r0; bfr[2][1] = r1; bfr[3][0] = r2; bfr[3][1] = r3;
        }
        #pragma unroll
        for (int mt = 0; mt < 2; mt++)
            #pragma unroll
            for (int nt = 0; nt < 4; nt++)
                mma_bf16(acc[mt][nt], a[mt], bfr[nt]);
    }
}

template<bool RELU, bool LAST>
__device__ __forceinline__ void mlp_store(char* smc, int outOff, float acc[2][4][4],
                                          int lane, int wr, int wc) {
    const float* biasf = (const float*)smc;
    float* sq_sm = (float*)(smc + 512);
    int r8 = lane >> 2, c2 = (lane & 3) << 1;
    #pragma unroll
    for (int mt = 0; mt < 2; mt++) {
        float srow[2] = {0.0f, 0.0f};
        #pragma unroll
        for (int nt = 0; nt < 4; nt++) {
            int col = wc*32 + nt*8 + c2;
            float b0 = biasf[col], b1 = biasf[col + 1];
            #pragma unroll
            for (int h8 = 0; h8 < 2; h8++) {
                float f0 = acc[mt][nt][h8*2]     + b0;
                float f1 = acc[mt][nt][h8*2 + 1] + b1;
                if (RELU) { f0 = fmaxf(f0, 0.0f); f1 = fmaxf(f1, 0.0f); }
                __nv_bfloat162 p = __float22bfloat162_rn(make_float2(f0, f1));
                uint32_t pk = *(const uint32_t*)&p;
                int r = wr*32 + mt*16 + h8*8 + r8;
                int chunk = wc*4 + nt;
                uint32_t off = (uint32_t)outOff + (uint32_t)r*RS
                             + (uint32_t)chunk*16 + (uint32_t)c2*2;
                *(uint32_t*)(smc + off) = pk;
                if (LAST) {
                    float2 fb = __bfloat1622float2(p);
                    srow[h8] += fb.x*fb.x + fb.y*fb.y;
                }
            }
        }
        if (LAST) {
            #pragma unroll
            for (int h8 = 0; h8 < 2; h8++) {
                float s = srow[h8];
                s += __shfl_xor_sync(0xffffffffu, s, 1);
                s += __shfl_xor_sync(0xffffffffu, s, 2);
                if ((lane & 3) == 0)
                    atomicAdd(&sq_sm[wr*32 + mt*16 + h8*8 + r8], s);
            }
        }
    }
}

__global__ void __launch_bounds__(256, 3)
k_mlp(const float* __restrict__ X, const float* __restrict__ b1,
      const float* __restrict__ b2, const float* __restrict__ b3) {
    extern __shared__ char smc[];
    float* biasf = (float*)smc;
    float* sq_sm = (float*)(smc + 512);
    float* red   = (float*)(smc + 768);

    int tid = threadIdx.x, wid = tid >> 5, lane = tid & 31;
    int wr = wid & 1, wc = wid >> 1;
    int r0 = blockIdx.x * 64;

    uint4* Au4 = (uint4*)(smc + MLP_A);
    uint4* Wu4 = (uint4*)(smc + MLP_W);

    const float4* src = (const float4*)(X + r0*DD);
    for (int e = tid; e < 1024; e += 256) {
        int row = e >> 4, c = e & 15;
        float4 v0 = src[row*32 + c*2];
        float4 v1 = src[row*32 + c*2 + 1];
        __nv_bfloat162 p0 = __float22bfloat162_rn(make_float2(v0.x, v0.y));
        __nv_bfloat162 p1 = __float22bfloat162_rn(make_float2(v0.z, v0.w));
        __nv_bfloat162 p2 = __float22bfloat162_rn(make_float2(v1.x, v1.y));
        __nv_bfloat162 p3 = __float22bfloat162_rn(make_float2(v1.z, v1.w));
        Au4[row*RSU4 + c] = make_uint4(*(const uint32_t*)&p0, *(const uint32_t*)&p1,
                                       *(const uint32_t*)&p2, *(const uint32_t*)&p3);
    }
    for (int e = tid; e < 2048; e += 256) Wu4[e + (e >> 4)] = ((const uint4*)g_wt[0])[e];
    if (tid < DD) biasf[tid] = b1[tid];
    if (tid < 64) sq_sm[tid] = 0.0f;
    __syncthreads();

    float acc[2][4][4];

    mlp_mma(smc, MLP_A, acc, lane, wr, wc);
    __syncthreads();
    mlp_store<true, false>(smc, MLP_B, acc, lane, wr, wc);
    for (int e = tid; e < 2048; e += 256) Wu4[e + (e >> 4)] = ((const uint4*)g_wt[1])[e];
    __syncthreads();
    if (tid < DD) biasf[tid] = b2[tid];
    __syncthreads();

    mlp_mma(smc, MLP_B, acc, lane, wr, wc);
    __syncthreads();
    mlp_store<true, false>(smc, MLP_A, acc, lane, wr, wc);
    for (int e = tid; e < 2048; e += 256) Wu4[e + (e >> 4)] = ((const uint4*)g_wt[2])[e];
    __syncthreads();
    if (tid < DD) biasf[tid] = b3[tid];
    __syncthreads();

    mlp_mma(smc, MLP_A, acc, lane, wr, wc);
    __syncthreads();
    mlp_store<false, true>(smc, MLP_B, acc, lane, wr, wc);
    __syncthreads();

    for (int e = tid; e < 1024; e += 256) {
        int row = e >> 4;
        ((uint4*)g_h)[(r0 + row)*16 + (e & 15)] = ((uint4*)(smc + MLP_B))[e + row];
    }
    if (tid < 64) {
        float sv = sq_sm[tid];
        g_sq[r0 + tid] = sv;
        sv += __shfl_xor_sync(0xffffffffu, sv, 16);
        sv += __shfl_xor_sync(0xffffffffu, sv, 8);
        sv += __shfl_xor_sync(0xffffffffu, sv, 4);
        sv += __shfl_xor_sync(0xffffffffu, sv, 2);
        sv += __shfl_xor_sync(0xffffffffu, sv, 1);
        if (lane == 0) red[wid] = sv;
    }
    __syncthreads();
    if (tid == 0) atomicAdd(&g_hsum, (double)(red[0] + red[1]));
}

// ---------------------------------------------------------------------------
// Pairwise: R12's exact 256-thread 128x128 tile compute (3 CTAs/SM, ~85 regs),
// but each CTA processes TWO j-tiles sequentially against a resident Hi:
// (bi,bj0) then (bi,bj0+1). 1056 CTAs. Hj buffer reloaded between tiles.
// Per-tile weights 1 (diag) / 2 (off-diag) applied to the thread sums.
// smem: header 4KB | Hi(128r) | Hj(128r) = 73728 B.
// ---------------------------------------------------------------------------
#define HI_OFF 4096
#define HJ_OFF (4096 + TILE128)
#define PAIR_SMEM (4096 + 2*TILE128)
#define P_SQI 64
#define P_SQJ0 576
#define P_SQJ1 1088
#define P_YI  1600
#define P_YJ0 2112
#define P_YJ1 2624

// one 128x128 tile: MMA + fused loss; returns this thread's weighted sum
__device__ __forceinline__ float pair_tile(char* smc, int sqjOff, int yjOff,
                                           float si[2][2], int li[2][2],
                                           uint32_t aA0, uint32_t bBase,
                                           int lane, int wc, float wgt) {
    float* sqj = (float*)(smc + sqjOff);
    int*   yj  = (int*)(smc + yjOff);
    int c2 = (lane & 3) << 1;
    float lsum = 0.0f;

    #pragma unroll 1
    for (int p = 0; p < 2; p++) {
        int gc = wc*64 + p*32;
        uint32_t bA0 = bBase + (uint32_t)gc*RS;

        float acc[2][4][4];
        #pragma unroll
        for (int mt = 0; mt < 2; mt++)
            #pragma unroll
            for (int nt = 0; nt < 4; nt++)
                #pragma unroll
                for (int k = 0; k < 4; k++) acc[mt][nt][k] = 0.0f;

        #pragma unroll
        for (int ks = 0; ks < 8; ks++) {
            uint32_t a[2][4];
            ldm_x4(a[0][0], a[0][1], a[0][2], a[0][3], aA0 + ks*32);
            ldm_x4(a[1][0], a[1][1], a[1][2], a[1][3], aA0 + 16*RS + ks*32);
            uint32_t bfr[4][2];
            {
                uint32_t r0, r1, r2, r3;
                ldm_x4(r0, r1, r2, r3, bA0 + ks*32);
                bfr[0][0] = r0; bfr[0][1] = r1; bfr[1][0] = r2; bfr[1][1] = r3;
                ldm_x4(r0, r1, r2, r3, bA0 + 16*RS + ks*32);
                bfr[2][0] = r0; bfr[2][1] = r1; bfr[3][0] = r2; bfr[3][1] = r3;
            }
            #pragma unroll
            for (int mt = 0; mt < 2; mt++)
                #pragma unroll
                for (int nt = 0; nt < 4; nt++)
                    mma_bf16(acc[mt][nt], a[mt], bfr[nt]);
        }

        int rare = 0;
        #pragma unroll
        for (int nt = 0; nt < 4; nt++)
            #pragma unroll
            for (int q = 0; q < 2; q++) {
                int col = gc + nt*8 + c2 + q;
                float sjv = sqj[col];
                int   ljv = yj[col];
                #pragma unroll
                for (int mt = 0; mt < 2; mt++)
                    #pragma unroll
                    for (int h = 0; h < 2; h++) {
                        float d = acc[mt][nt][h*2 + q];
                        float dist = fmaf(-2.0f, d, si[mt][h] + sjv);
                        bool  eq = (li[mt][h] == ljv);
                        lsum += eq ? dist : FARV;
                        rare |= (!eq && dist < 18.0f);
                    }
            }
        if (__any_sync(0xffffffffu, rare)) {
            #pragma unroll
            for (int nt = 0; nt < 4; nt++)
                #pragma unroll
                for (int q = 0; q < 2; q++) {
                    int col = gc + nt*8 + c2 + q;
                    float sjv = sqj[col];
                    int   ljv = yj[col];
                    #pragma unroll
                    for (int mt = 0; mt < 2; mt++)
                        #pragma unroll
                        for (int h = 0; h < 2; h++) {
                            float d = acc[mt][nt][h*2 + q];
                            float dist = fmaxf(fmaf(-2.0f, d, si[mt][h] + sjv), 0.0f);
                            bool  eq = (li[mt][h] == ljv);
                            if (!eq && dist < 18.0f)
                                lsum += (-logf(1.01f - expf(-dist))) - FARV;
                        }
                }
        }
    }
    return wgt * lsum;
}

__global__ void __launch_bounds__(256, 3)
k_pair(const int* __restrict__ y, float* __restrict__ out) {
    extern __shared__ char smc[];
    float* redf = (float*)(smc + 16);
    float* sqi  = (float*)(smc + P_SQI);

    int tid = threadIdx.x, wid = tid >> 5, lane = tid & 31;
    int wr = wid & 3, wc = wid >> 2;

    // unit -> (bi, bj0); j tiles bj0, bj0+1 (if present)
    int rem = blockIdx.x, bi = 0;
    while (true) {
        int np = (65 - bi) >> 1;
        if (rem < np) break;
        rem -= np; bi++;
    }
    int bj0 = bi + 2*rem;
    bool has2 = (bj0 + 1 < NT);
    float w0f = (bj0 == bi) ? 1.0f : 2.0f;

    const uint4* gh = (const uint4*)g_h;
    uint4* Hi = (uint4*)(smc + HI_OFF);
    uint4* Hj = (uint4*)(smc + HJ_OFF);
    for (int e = tid; e < 2048; e += 256) {
        int pad = e >> 4;
        Hi[e + pad] = gh[bi*2048 + e];
        Hj[e + pad] = gh[bj0*2048 + e];
    }
    if (tid < 128) {
        sqi[tid] = g_sq[bi*128 + tid];
        ((int*)(smc + P_YI))[tid] = y[bi*128 + tid];
        ((float*)(smc + P_SQJ0))[tid] = g_sq[bj0*128 + tid];
        ((int*)(smc + P_YJ0))[tid]    = y[bj0*128 + tid];
        if (has2) {
            ((float*)(smc + P_SQJ1))[tid] = g_sq[(bj0+1)*128 + tid];
            ((int*)(smc + P_YJ1))[tid]    = y[(bj0+1)*128 + tid];
        }
    }
    __syncthreads();

    uint32_t hiB = smem_to_u32(smc + HI_OFF);
    uint32_t hjB = smem_to_u32(smc + HJ_OFF);
    int bg = lane >> 3;
    uint32_t aA0 = hiB + (uint32_t)(wr*32 + (lane & 15))*RS + (uint32_t)(lane >> 4)*16;
    uint32_t bBase = hjB + (uint32_t)(((bg >> 1) << 3) + (lane & 7))*RS
                   + (uint32_t)(bg & 1)*16;

    int r8 = lane >> 2;
    float si[2][2]; int li[2][2];
    #pragma unroll
    for (int mt = 0; mt < 2; mt++)
        #pragma unroll
        for (int h = 0; h < 2; h++) {
            int row = wr*32 + mt*16 + h*8 + r8;
            si[mt][h] = sqi[row];
            li[mt][h] = ((int*)(smc + P_YI))[row];
        }

    float lsum = pair_tile(smc, P_SQJ0, P_YJ0, si, li, aA0, bBase, lane, wc, w0f);

    if (has2) {
        __syncthreads();   // all warps done reading Hj tile 0
        for (int e = tid; e < 2048; e += 256)
            Hj[e + (e >> 4)] = gh[(bj0+1)*2048 + e];
        __syncthreads();
        lsum += pair_tile(smc, P_SQJ1, P_YJ1, si, li, aA0, bBase, lane, wc, 2.0f);
    }

    lsum += __shfl_xor_sync(0xffffffffu, lsum, 1);
    lsum += __shfl_xor_sync(0xffffffffu, lsum, 2);
    lsum += __shfl_xor_sync(0xffffffffu, lsum, 4);
    lsum += __shfl_xor_sync(0xffffffffu, lsum, 8);
    lsum += __shfl_xor_sync(0xffffffffu, lsum, 16);
    if (lane == 0) redf[wid] = lsum;
    __syncthreads();
    if (tid == 0) {
        double tot = 0.0;
        for (int w = 0; w < 8; w++) tot += (double)redf[w];
        atomicAdd(&g_loss, tot);
        __threadfence();
        unsigned tk = atomicAdd(&g_ticket, 1u);
        if (tk == NPAIRU - 1) {
            __threadfence();
            double lt = atomicAdd(&g_loss, 0.0);
            double hs = atomicAdd(&g_hsum, 0.0);
            double loss = lt / ((double)BN * (double)BN);
            loss += 0.01 * (hs / ((double)BN * (double)DD));
            out[0] = (float)loss;
        }
    }
}

// ---------------------------------------------------------------------------

extern "C" void kernel_launch(void* const* d_in, const int* in_sizes, int n_in,
                              void* d_out, int out_size) {
    (void)in_sizes; (void)n_in; (void)out_size;
    const float* X  = (const float*)d_in[0];
    const float* W1 = (const float*)d_in[1];
    const float* b1 = (const float*)d_in[2];
    const float* W2 = (const float*)d_in[3];
    const float* b2 = (const float*)d_in[4];
    const float* W3 = (const float*)d_in[5];
    const float* b3 = (const float*)d_in[6];
    const int*   y  = (const int*)d_in[7];

    cudaFuncSetAttribute(k_mlp,  cudaFuncAttributeMaxDynamicSharedMemorySize, MLP_SMEM);
    cudaFuncSetAttribute(k_pair, cudaFuncAttributeMaxDynamicSharedMemorySize, PAIR_SMEM);

    k_prep<<<48, 256>>>(W1, W2, W3);
    k_mlp<<<BN/64, 256, MLP_SMEM>>>(X, b1, b2, b3);
    k_pair<<<NPAIRU, 256, PAIR_SMEM>>>(y, (float*)d_out);
}

// round 15
// speedup vs baseline: 1.4958x; 1.0648x over previous
#include <cuda_runtime.h>
#include <cuda_bf16.h>
#include <math.h>
#include <cstdint>

#define BN 8192
#define DD 128
#define NT (BN/128)                 // 64 tiles per dim
#define NBLK (NT*(NT+1)/2)          // 2080 triangular tiles
#define FARV (-0.00995033085316808285f)

#define RS   272                    // padded smem row stride (bytes)
#define RSU4 17
#define TILE128 (128*RS)            // 34816 B
#define TILE64  (64*RS)

// Device state. g_h / g_wt are PLAIN row-major bf16 (256B rows); padding is
// applied when staging into smem (dst uint4 index = e + (e>>4)).
__device__ __nv_bfloat16 g_h[BN*DD];
__device__ __nv_bfloat16 g_wt[3][DD*DD];   // row n = column n of W
__device__ float  g_sq[BN];
__device__ double g_loss;
__device__ double g_hsum;
__device__ unsigned g_ticket;

// ---------------- warp-MMA helpers (plain sm_80+ PTX) ----------------------
__device__ __forceinline__ void ldm_x4(uint32_t& r0, uint32_t& r1,
                                       uint32_t& r2, uint32_t& r3, uint32_t addr) {
    asm volatile("ldmatrix.sync.aligned.m8n8.x4.shared.b16 {%0,%1,%2,%3}, [%4];"
                 : "=r"(r0), "=r"(r1), "=r"(r2), "=r"(r3) : "r"(addr));
}
__device__ __forceinline__ void mma_bf16(float* d, const uint32_t* a, const uint32_t* b) {
    asm volatile("mma.sync.aligned.m16n8k16.row.col.f32.bf16.bf16.f32 "
                 "{%0,%1,%2,%3}, {%4,%5,%6,%7}, {%8,%9}, {%0,%1,%2,%3};"
                 : "+f"(d[0]), "+f"(d[1]), "+f"(d[2]), "+f"(d[3])
                 : "r"(a[0]), "r"(a[1]), "r"(a[2]), "r"(a[3]), "r"(b[0]), "r"(b[1]));
}
__device__ __forceinline__ uint32_t smem_to_u32(const void* p) {
    uint32_t a;
    asm("{ .reg .u64 t; cvta.to.shared.u64 t, %1; cvt.u32.u64 %0, t; }" : "=r"(a) : "l"(p));
    return a;
}

// ---------------------------------------------------------------------------
// Prep (48 CTAs): CTA (w, s) transposes k-slice [8s, 8s+8) of W_w.
// ---------------------------------------------------------------------------
__global__ void __launch_bounds__(256)
k_prep(const float* __restrict__ W1, const float* __restrict__ W2,
       const float* __restrict__ W3) {
    __shared__ float stage[8*DD];      // 4KB
    int tid = threadIdx.x;
    int w = blockIdx.x >> 4, s = blockIdx.x & 15;
    const float* W = (w == 0) ? W1 : (w == 1) ? W2 : W3;
    if (tid < 256) ((float4*)stage)[tid] = ((const float4*)W)[s*256 + tid];
    __syncthreads();
    if (tid < 128) {
        int n = tid;
        uint32_t pk[4];
        #pragma unroll
        for (int p = 0; p < 4; p++) {
            float lo = stage[(2*p    ) * DD + n];
            float hi = stage[(2*p + 1) * DD + n];
            __nv_bfloat162 h2 = __float22bfloat162_rn(make_float2(lo, hi));
            pk[p] = *(const uint32_t*)&h2;
        }
        ((uint4*)g_wt[w])[n*16 + s] = make_uint4(pk[0], pk[1], pk[2], pk[3]);
    }
    if (blockIdx.x == 0 && tid == 0) { g_loss = 0.0; g_hsum = 0.0; g_ticket = 0u; }
}

// ---------------------------------------------------------------------------
// Tensor-core MLP: 128 CTAs x 64 rows; 8 warps as 2x4 (wr rows, wc cols).
// Padded-row affine layout, fully unrolled k loop. 3 CTAs/SM.
// ---------------------------------------------------------------------------
#define MLP_A 1024
#define MLP_B (1024 + TILE64)
#define MLP_W (1024 + 2*TILE64)
#define MLP_SMEM (1024 + 2*TILE64 + TILE128)

__device__ __forceinline__ void mlp_mma(const char* smc, int aOff, float acc[2][4][4],
                                        int lane, int wr, int wc) {
    uint32_t aB = smem_to_u32(smc + aOff);
    uint32_t wB = smem_to_u32(smc + MLP_W);
    #pragma unroll
    for (int mt = 0; mt < 2; mt++)
        #pragma unroll
        for (int nt = 0; nt < 4; nt++)
            #pragma unroll
            for (int k = 0; k < 4; k++) acc[mt][nt][k] = 0.0f;

    int bg = lane >> 3;
    uint32_t aA0 = aB + (uint32_t)(wr*32 + (lane & 15))*RS + (uint32_t)(lane >> 4)*16;
    uint32_t bA0 = wB + (uint32_t)(wc*32 + ((bg >> 1) << 3) + (lane & 7))*RS
                 + (uint32_t)(bg & 1)*16;

    #pragma unroll
    for (int ks = 0; ks < 8; ks++) {
        uint32_t a[2][4];
        ldm_x4(a[0][0], a[0][1], a[0][2], a[0][3], aA0 + ks*32);
        ldm_x4(a[1][0], a[1][1], a[1][2], a[1][3], aA0 + 16*RS + ks*32);
        uint32_t bfr[4][2];
        {
            uint32_t r0, r1, r2, r3;
            ldm_x4(r0, r1, r2, r3, bA0 + ks*32);
            bfr[0][0] = r0; bfr[0][1] = r1; bfr[1][0] = r2; bfr[1][1] = r3;
            ldm_x4(r0, r1, r2, r3, bA0 + 16*RS + ks*32);
            bfr[2][0] = r0; bfr[2][1] = r1; bfr[3][0] = r2; bfr[3][1] = r3;
        }
        #pragma unroll
        for (int mt = 0; mt < 2; mt++)
            #pragma unroll
            for (int nt = 0; nt < 4; nt++)
                mma_bf16(acc[mt][nt], a[mt], bfr[nt]);
    }
}

template<bool RELU, bool LAST>
__device__ __forceinline__ void mlp_store(char* smc, int outOff, float acc[2][4][4],
                                          int lane, int wr, int wc) {
    const float* biasf = (const float*)smc;
    float* sq_sm = (float*)(smc + 512);
    int r8 = lane >> 2, c2 = (lane & 3) << 1;
    #pragma unroll
    for (int mt = 0; mt < 2; mt++) {
        float srow[2] = {0.0f, 0.0f};
        #pragma unroll
        for (int nt = 0; nt < 4; nt++) {
            int col = wc*32 + nt*8 + c2;
            float b0 = biasf[col], b1 = biasf[col + 1];
            #pragma unroll
            for (int h8 = 0; h8 < 2; h8++) {
                float f0 = acc[mt][nt][h8*2]     + b0;
                float f1 = acc[mt][nt][h8*2 + 1] + b1;
                if (RELU) { f0 = fmaxf(f0, 0.0f); f1 = fmaxf(f1, 0.0f); }
                __nv_bfloat162 p = __float22bfloat162_rn(make_float2(f0, f1));
                uint32_t pk = *(const uint32_t*)&p;
                int r = wr*32 + mt*16 + h8*8 + r8;
                int chunk = wc*4 + nt;
                uint32_t off = (uint32_t)outOff + (uint32_t)r*RS
                             + (uint32_t)chunk*16 + (uint32_t)c2*2;
                *(uint32_t*)(smc + off) = pk;
                if (LAST) {
                    float2 fb = __bfloat1622float2(p);
                    srow[h8] += fb.x*fb.x + fb.y*fb.y;
                }
            }
        }
        if (LAST) {
            #pragma unroll
            for (int h8 = 0; h8 < 2; h8++) {
                float s = srow[h8];
                s += __shfl_xor_sync(0xffffffffu, s, 1);
                s += __shfl_xor_sync(0xffffffffu, s, 2);
                if ((lane & 3) == 0)
                    atomicAdd(&sq_sm[wr*32 + mt*16 + h8*8 + r8], s);
            }
        }
    }
}

__global__ void __launch_bounds__(256, 3)
k_mlp(const float* __restrict__ X, const float* __restrict__ b1,
      const float* __restrict__ b2, const float* __restrict__ b3) {
    extern __shared__ char smc[];
    float* biasf = (float*)smc;
    float* sq_sm = (float*)(smc + 512);
    float* red   = (float*)(smc + 768);

    int tid = threadIdx.x, wid = tid >> 5, lane = tid & 31;
    int wr = wid & 1, wc = wid >> 1;
    int r0 = blockIdx.x * 64;

    uint4* Au4 = (uint4*)(smc + MLP_A);
    uint4* Wu4 = (uint4*)(smc + MLP_W);

    const float4* src = (const float4*)(X + r0*DD);
    for (int e = tid; e < 1024; e += 256) {
        int row = e >> 4, c = e & 15;
        float4 v0 = src[row*32 + c*2];
        float4 v1 = src[row*32 + c*2 + 1];
        __nv_bfloat162 p0 = __float22bfloat162_rn(make_float2(v0.x, v0.y));
        __nv_bfloat162 p1 = __float22bfloat162_rn(make_float2(v0.z, v0.w));
        __nv_bfloat162 p2 = __float22bfloat162_rn(make_float2(v1.x, v1.y));
        __nv_bfloat162 p3 = __float22bfloat162_rn(make_float2(v1.z, v1.w));
        Au4[row*RSU4 + c] = make_uint4(*(const uint32_t*)&p0, *(const uint32_t*)&p1,
                                       *(const uint32_t*)&p2, *(const uint32_t*)&p3);
    }
    for (int e = tid; e < 2048; e += 256) Wu4[e + (e >> 4)] = ((const uint4*)g_wt[0])[e];
    if (tid < DD) biasf[tid] = b1[tid];
    if (tid < 64) sq_sm[tid] = 0.0f;
    __syncthreads();

    float acc[2][4][4];

    mlp_mma(smc, MLP_A, acc, lane, wr, wc);
    __syncthreads();
    mlp_store<true, false>(smc, MLP_B, acc, lane, wr, wc);
    for (int e = tid; e < 2048; e += 256) Wu4[e + (e >> 4)] = ((const uint4*)g_wt[1])[e];
    __syncthreads();
    if (tid < DD) biasf[tid] = b2[tid];
    __syncthreads();

    mlp_mma(smc, MLP_B, acc, lane, wr, wc);
    __syncthreads();
    mlp_store<true, false>(smc, MLP_A, acc, lane, wr, wc);
    for (int e = tid; e < 2048; e += 256) Wu4[e + (e >> 4)] = ((const uint4*)g_wt[2])[e];
    __syncthreads();
    if (tid < DD) biasf[tid] = b3[tid];
    __syncthreads();

    mlp_mma(smc, MLP_A, acc, lane, wr, wc);
    __syncthreads();
    mlp_store<false, true>(smc, MLP_B, acc, lane, wr, wc);
    __syncthreads();

    for (int e = tid; e < 1024; e += 256) {
        int row = e >> 4;
        ((uint4*)g_h)[(r0 + row)*16 + (e & 15)] = ((uint4*)(smc + MLP_B))[e + row];
    }
    if (tid < 64) {
        float sv = sq_sm[tid];
        g_sq[r0 + tid] = sv;
        sv += __shfl_xor_sync(0xffffffffu, sv, 16);
        sv += __shfl_xor_sync(0xffffffffu, sv, 8);
        sv += __shfl_xor_sync(0xffffffffu, sv, 4);
        sv += __shfl_xor_sync(0xffffffffu, sv, 2);
        sv += __shfl_xor_sync(0xffffffffu, sv, 1);
        if (lane == 0) red[wid] = sv;
    }
    __syncthreads();
    if (tid == 0) atomicAdd(&g_hsum, (double)(red[0] + red[1]));
}

// ---------------------------------------------------------------------------
// Pairwise (R12 exact): one 128x128 tile per CTA, 2080 CTAs. Padded-row
// layout, full unroll, n-split into two halves (acc 32 regs) => 3 CTAs/SM.
// smem: header 4KB | Hi(128r) | Hj(128r) = 73728 B
// ---------------------------------------------------------------------------
#define HI_OFF 4096
#define HJ_OFF (4096 + TILE128)
#define PAIR_SMEM (4096 + 2*TILE128)

__global__ void __launch_bounds__(256, 3)
k_pair(const int* __restrict__ y, float* __restrict__ out) {
    extern __shared__ char smc[];
    float* redf = (float*)(smc + 16);
    float* sqi  = (float*)(smc + 64);
    float* sqj  = (float*)(smc + 576);
    int*   yi   = (int*)(smc + 1088);
    int*   yj   = (int*)(smc + 1600);

    int tid = threadIdx.x, wid = tid >> 5, lane = tid & 31;
    int wr = wid & 3, wc = wid >> 2;

    // triangular tile mapping: block t -> (bi, bj) with bi <= bj
    int t = blockIdx.x;
    float nf = (float)NT + 0.5f;
    int bi = (int)(nf - sqrtf(nf*nf - 2.0f*(float)t));
    if (bi < 0) bi = 0;
    if (bi >= NT) bi = NT - 1;
    while (bi*NT - (bi*(bi-1))/2 > t) bi--;
    while ((bi+1)*NT - ((bi+1)*bi)/2 <= t) bi++;
    int bj = bi + (t - (bi*NT - (bi*(bi-1))/2));

    // tile loads: plain g_h rows -> padded smem
    const uint4* gh = (const uint4*)g_h;
    uint4* Hi = (uint4*)(smc + HI_OFF);
    uint4* Hj = (uint4*)(smc + HJ_OFF);
    for (int e = tid; e < 2048; e += 256) {
        int pad = e >> 4;
        Hi[e + pad] = gh[bi*2048 + e];
        Hj[e + pad] = gh[bj*2048 + e];
    }
    if (tid < 128) {
        sqi[tid] = g_sq[bi*128 + tid];
        sqj[tid] = g_sq[bj*128 + tid];
        yi[tid]  = y[bi*128 + tid];
        yj[tid]  = y[bj*128 + tid];
    }
    __syncthreads();

    uint32_t hiB = smem_to_u32(smc + HI_OFF);
    uint32_t hjB = smem_to_u32(smc + HJ_OFF);

    int bg = lane >> 3;
    uint32_t aA0 = hiB + (uint32_t)(wr*32 + (lane & 15))*RS + (uint32_t)(lane >> 4)*16;
    uint32_t bBase = hjB + (uint32_t)(((bg >> 1) << 3) + (lane & 7))*RS
                   + (uint32_t)(bg & 1)*16;

    int r8 = lane >> 2, c2 = (lane & 3) << 1;
    float si[2][2]; int li[2][2];
    #pragma unroll
    for (int mt = 0; mt < 2; mt++)
        #pragma unroll
        for (int h = 0; h < 2; h++) {
            int row = wr*32 + mt*16 + h*8 + r8;
            si[mt][h] = sqi[row];
            li[mt][h] = yi[row];
        }

    float lsum = 0.0f;

    #pragma unroll 1
    for (int p = 0; p < 2; p++) {
        uint32_t bA0 = bBase + (uint32_t)(wc*64 + p*32)*RS;

        float acc[2][4][4];
        #pragma unroll
        for (int mt = 0; mt < 2; mt++)
            #pragma unroll
            for (int nt = 0; nt < 4; nt++)
                #pragma unroll
                for (int k = 0; k < 4; k++) acc[mt][nt][k] = 0.0f;

        #pragma unroll
        for (int ks = 0; ks < 8; ks++) {
            uint32_t a[2][4];
            ldm_x4(a[0][0], a[0][1], a[0][2], a[0][3], aA0 + ks*32);
            ldm_x4(a[1][0], a[1][1], a[1][2], a[1][3], aA0 + 16*RS + ks*32);
            uint32_t bfr[4][2];
            {
                uint32_t r0, r1, r2, r3;
                ldm_x4(r0, r1, r2, r3, bA0 + ks*32);
                bfr[0][0] = r0; bfr[0][1] = r1; bfr[1][0] = r2; bfr[1][1] = r3;
                ldm_x4(r0, r1, r2, r3, bA0 + 16*RS + ks*32);
                bfr[2][0] = r0; bfr[2][1] = r1; bfr[3][0] = r2; bfr[3][1] = r3;
            }
            #pragma unroll
            for (int mt = 0; mt < 2; mt++)
                #pragma unroll
                for (int nt = 0; nt < 4; nt++)
                    mma_bf16(acc[mt][nt], a[mt], bfr[nt]);
        }

        // epilogue for this half
        float sj[4][2]; int lj[4][2];
        #pragma unroll
        for (int nt = 0; nt < 4; nt++)
            #pragma unroll
            for (int q = 0; q < 2; q++) {
                int col = wc*64 + p*32 + nt*8 + c2 + q;
                sj[nt][q] = sqj[col];
                lj[nt][q] = yj[col];
            }

        int rare = 0;
        #pragma unroll
        for (int mt = 0; mt < 2; mt++)
            #pragma unroll
            for (int nt = 0; nt < 4; nt++)
                #pragma unroll
                for (int h = 0; h < 2; h++)
                    #pragma unroll
                    for (int q = 0; q < 2; q++) {
                        float d = acc[mt][nt][h*2 + q];
                        float dist = fmaf(-2.0f, d, si[mt][h] + sj[nt][q]);
                        bool  eq = (li[mt][h] == lj[nt][q]);
                        lsum += eq ? dist : FARV;
                        rare |= (!eq && dist < 18.0f);
                    }
        if (__any_sync(0xffffffffu, rare)) {
            #pragma unroll
            for (int mt = 0; mt < 2; mt++)
                #pragma unroll
                for (int nt = 0; nt < 4; nt++)
                    #pragma unroll
                    for (int h = 0; h < 2; h++)
                        #pragma unroll
                        for (int q = 0; q < 2; q++) {
                            float d = acc[mt][nt][h*2 + q];
                            float dist = fmaxf(fmaf(-2.0f, d, si[mt][h] + sj[nt][q]), 0.0f);
                            bool  eq = (li[mt][h] == lj[nt][q]);
                            if (!eq && dist < 18.0f)
                                lsum += (-logf(1.01f - expf(-dist))) - FARV;
                        }
        }
    }

    lsum += __shfl_xor_sync(0xffffffffu, lsum, 1);
    lsum += __shfl_xor_sync(0xffffffffu, lsum, 2);
    lsum += __shfl_xor_sync(0xffffffffu, lsum, 4);
    lsum += __shfl_xor_sync(0xffffffffu, lsum, 8);
    lsum += __shfl_xor_sync(0xffffffffu, lsum, 16);
    if (lane == 0) redf[wid] = lsum;
    __syncthreads();
    if (tid == 0) {
        double tot = 0.0;
        for (int w = 0; w < 8; w++) tot += (double)redf[w];
        if (bi != bj) tot *= 2.0;
        atomicAdd(&g_loss, tot);
        __threadfence();
        unsigned tk = atomicAdd(&g_ticket, 1u);
        if (tk == NBLK - 1) {
            __threadfence();
            double lt = atomicAdd(&g_loss, 0.0);
            double hs = atomicAdd(&g_hsum, 0.0);
            double loss = lt / ((double)BN * (double)BN);
            loss += 0.01 * (hs / ((double)BN * (double)DD));
            out[0] = (float)loss;
        }
    }
}

// ---------------------------------------------------------------------------

extern "C" void kernel_launch(void* const* d_in, const int* in_sizes, int n_in,
                              void* d_out, int out_size) {
    (void)in_sizes; (void)n_in; (void)out_size;
    const float* X  = (const float*)d_in[0];
    const float* W1 = (const float*)d_in[1];
    const float* b1 = (const float*)d_in[2];
    const float* W2 = (const float*)d_in[3];
    const float* b2 = (const float*)d_in[4];
    const float* W3 = (const float*)d_in[5];
    const float* b3 = (const float*)d_in[6];
    const int*   y  = (const int*)d_in[7];

    cudaFuncSetAttribute(k_mlp,  cudaFuncAttributeMaxDynamicSharedMemorySize, MLP_SMEM);
    cudaFuncSetAttribute(k_pair, cudaFuncAttributeMaxDynamicSharedMemorySize, PAIR_SMEM);

    k_prep<<<48, 256>>>(W1, W2, W3);
    k_mlp<<<BN/64, 256, MLP_SMEM>>>(X, b1, b2, b3);
    k_pair<<<NBLK, 256, PAIR_SMEM>>>(y, (float*)d_out);
}

// round 17
// speedup vs baseline: 1.5352x; 1.0264x over previous
#include <cuda_runtime.h>
#include <cuda_bf16.h>
#include <math.h>
#include <cstdint>

#define BN 8192
#define DD 128
#define NT (BN/128)                 // 64 tiles per dim
#define NBLK (NT*(NT+1)/2)          // 2080 triangular tiles
#define FARV (-0.00995033085316808285f)

#define RS   272                    // padded smem row stride (bytes)
#define RSU4 17
#define TILE128 (128*RS)            // 34816 B
#define TILE64  (64*RS)

// Device state. g_h / g_wt are PLAIN row-major bf16 (256B rows); padding is
// applied when staging into smem (dst uint4 index = e + (e>>4)).
// All mutable state is zero-initialized at load and reset by the pair
// finalizer at the end of every run (graph replays see clean state).
__device__ __nv_bfloat16 g_h[BN*DD];
__device__ __nv_bfloat16 g_wt[3][DD*DD];   // row n = column n of W
__device__ float  g_sq[BN];
__device__ double g_loss;
__device__ double g_hsum;
__device__ unsigned g_ticket;
__device__ unsigned g_wcnt[3];
__device__ unsigned g_wdone[3];

// ---------------- warp-MMA helpers (plain sm_80+ PTX) ----------------------
__device__ __forceinline__ void ldm_x4(uint32_t& r0, uint32_t& r1,
                                       uint32_t& r2, uint32_t& r3, uint32_t addr) {
    asm volatile("ldmatrix.sync.aligned.m8n8.x4.shared.b16 {%0,%1,%2,%3}, [%4];"
                 : "=r"(r0), "=r"(r1), "=r"(r2), "=r"(r3) : "r"(addr));
}
__device__ __forceinline__ void mma_bf16(float* d, const uint32_t* a, const uint32_t* b) {
    asm volatile("mma.sync.aligned.m16n8k16.row.col.f32.bf16.bf16.f32 "
                 "{%0,%1,%2,%3}, {%4,%5,%6,%7}, {%8,%9}, {%0,%1,%2,%3};"
                 : "+f"(d[0]), "+f"(d[1]), "+f"(d[2]), "+f"(d[3])
                 : "r"(a[0]), "r"(a[1]), "r"(a[2]), "r"(a[3]), "r"(b[0]), "r"(b[1]));
}
__device__ __forceinline__ uint32_t smem_to_u32(const void* p) {
    uint32_t a;
    asm("{ .reg .u64 t; cvta.to.shared.u64 t, %1; cvt.u32.u64 %0, t; }" : "=r"(a) : "l"(p));
    return a;
}
__device__ __forceinline__ void cp16(uint32_t dst, const void* src) {
    asm volatile("cp.async.cg.shared.global [%0], [%1], 16;"
                 :: "r"(dst), "l"(src) : "memory");
}
#define CP_COMMIT() asm volatile("cp.async.commit_group;" ::: "memory")
#define CP_WAIT(n)  asm volatile("cp.async.wait_group %0;" :: "n"(n) : "memory")

__device__ __forceinline__ void wait_flag(unsigned* f) {
    if (threadIdx.x == 0) {
        while (atomicAdd(f, 0u) == 0u) __nanosleep(64);
        __threadfence();
    }
    __syncthreads();
}

// ---------------------------------------------------------------------------
// Tensor-core MLP + embedded W-transpose. grid=128 (1 wave, ~1 CTA/SM).
// smem: bias[384f] | sq[64f] | red | A(64r) | B(64r) | WA(128r) | WB(128r)
// CTAs 0..47 transpose W slices first (flag-signaled); everyone overlaps
// X-load with that. W2/W3 are cp.async-prefetched behind L1/L2 MMA.
// ---------------------------------------------------------------------------
#define MH_SQ   1536
#define MH_RED  1792
#define MLP_A   2048
#define MLP_B   (2048 + TILE64)
#define MLP_WA  (2048 + 2*TILE64)
#define MLP_WB  (2048 + 2*TILE64 + TILE128)
#define MLP_SMEM (2048 + 2*TILE64 + 2*TILE128)   // 106496 B

__device__ __forceinline__ void mlp_mma(const char* smc, int aOff, int wOff,
                                        float acc[2][4][4], int lane, int wr, int wc) {
    uint32_t aB = smem_to_u32(smc + aOff);
    uint32_t wB = smem_to_u32(smc + wOff);
    #pragma unroll
    for (int mt = 0; mt < 2; mt++)
        #pragma unroll
        for (int nt = 0; nt < 4; nt++)
            #pragma unroll
            for (int k = 0; k < 4; k++) acc[mt][nt][k] = 0.0f;

    int bg = lane >> 3;
    uint32_t aA0 = aB + (uint32_t)(wr*32 + (lane & 15))*RS + (uint32_t)(lane >> 4)*16;
    uint32_t bA0 = wB + (uint32_t)(wc*32 + ((bg >> 1) << 3) + (lane & 7))*RS
                 + (uint32_t)(bg & 1)*16;

    #pragma unroll
    for (int ks = 0; ks < 8; ks++) {
        uint32_t a[2][4];
        ldm_x4(a[0][0], a[0][1], a[0][2], a[0][3], aA0 + ks*32);
        ldm_x4(a[1][0], a[1][1], a[1][2], a[1][3], aA0 + 16*RS + ks*32);
        uint32_t bfr[4][2];
        {
            uint32_t r0, r1, r2, r3;
            ldm_x4(r0, r1, r2, r3, bA0 + ks*32);
            bfr[0][0] = r0; bfr[0][1] = r1; bfr[1][0] = r2; bfr[1][1] = r3;
            ldm_x4(r0, r1, r2, r3, bA0 + 16*RS + ks*32);
            bfr[2][0] = r0; bfr[2][1] = r1; bfr[3][0] = r2; bfr[3][1] = r3;
        }
        #pragma unroll
        for (int mt = 0; mt < 2; mt++)
            #pragma unroll
            for (int nt = 0; nt < 4; nt++)
                mma_bf16(acc[mt][nt], a[mt], bfr[nt]);
    }
}

template<bool RELU, bool LAST>
__device__ __forceinline__ void mlp_store(char* smc, int outOff, float acc[2][4][4],
                                          const float* biasf, int lane, int wr, int wc) {
    float* sq_sm = (float*)(smc + MH_SQ);
    int r8 = lane >> 2, c2 = (lane & 3) << 1;
    #pragma unroll
    for (int mt = 0; mt < 2; mt++) {
        float srow[2] = {0.0f, 0.0f};
        #pragma unroll
        for (int nt = 0; nt < 4; nt++) {
            int col = wc*32 + nt*8 + c2;
            float b0 = biasf[col], b1 = biasf[col + 1];
            #pragma unroll
            for (int h8 = 0; h8 < 2; h8++) {
                float f0 = acc[mt][nt][h8*2]     + b0;
                float f1 = acc[mt][nt][h8*2 + 1] + b1;
                if (RELU) { f0 = fmaxf(f0, 0.0f); f1 = fmaxf(f1, 0.0f); }
                __nv_bfloat162 p = __float22bfloat162_rn(make_float2(f0, f1));
                uint32_t pk = *(const uint32_t*)&p;
                int r = wr*32 + mt*16 + h8*8 + r8;
                int chunk = wc*4 + nt;
                uint32_t off = (uint32_t)outOff + (uint32_t)r*RS
                             + (uint32_t)chunk*16 + (uint32_t)c2*2;
                *(uint32_t*)(smc + off) = pk;
                if (LAST) {
                    float2 fb = __bfloat1622float2(p);
                    srow[h8] += fb.x*fb.x + fb.y*fb.y;
                }
            }
        }
        if (LAST) {
            #pragma unroll
            for (int h8 = 0; h8 < 2; h8++) {
                float s = srow[h8];
                s += __shfl_xor_sync(0xffffffffu, s, 1);
                s += __shfl_xor_sync(0xffffffffu, s, 2);
                if ((lane & 3) == 0)
                    atomicAdd(&sq_sm[wr*32 + mt*16 + h8*8 + r8], s);
            }
        }
    }
}

__global__ void __launch_bounds__(256)
k_mlp(const float* __restrict__ X,
      const float* __restrict__ W1, const float* __restrict__ b1,
      const float* __restrict__ W2, const float* __restrict__ b2,
      const float* __restrict__ W3, const float* __restrict__ b3) {
    extern __shared__ char smc[];
    float* bias  = (float*)smc;            // [0:384) floats: b1|b2|b3
    float* sq_sm = (float*)(smc + MH_SQ);
    float* red   = (float*)(smc + MH_RED);

    int tid = threadIdx.x, wid = tid >> 5, lane = tid & 31;
    int wr = wid & 1, wc = wid >> 1;
    int r0 = blockIdx.x * 64;

    // phase 0: CTAs 0..47 transpose one 8-row k-slice of one W
    if (blockIdx.x < 48) {
        float* stage = (float*)(smc + MLP_A);    // 4KB scratch in A region
        int w = blockIdx.x >> 4, s = blockIdx.x & 15;
        const float* W = (w == 0) ? W1 : (w == 1) ? W2 : W3;
        ((float4*)stage)[tid] = ((const float4*)W)[s*256 + tid];
        __syncthreads();
        if (tid < 128) {
            uint32_t pk[4];
            #pragma unroll
            for (int p = 0; p < 4; p++) {
                float lo = stage[(2*p    ) * DD + tid];
                float hi = stage[(2*p + 1) * DD + tid];
                __nv_bfloat162 h2 = __float22bfloat162_rn(make_float2(lo, hi));
                pk[p] = *(const uint32_t*)&h2;
            }
            ((uint4*)g_wt[w])[tid*16 + s] = make_uint4(pk[0], pk[1], pk[2], pk[3]);
        }
        __threadfence();
        __syncthreads();
        if (tid == 0) {
            unsigned old = atomicAdd(&g_wcnt[w], 1u);
            if (old == 15u) atomicExch(&g_wdone[w], 1u);
        }
        __syncthreads();
    }

    // X -> A (fp32 coalesced load, bf16 RN round, padded store)
    const float4* src = (const float4*)(X + r0*DD);
    uint4* Au4 = (uint4*)(smc + MLP_A);
    for (int e = tid; e < 1024; e += 256) {
        int row = e >> 4, c = e & 15;
        float4 v0 = src[row*32 + c*2];
        float4 v1 = src[row*32 + c*2 + 1];
        __nv_bfloat162 p0 = __float22bfloat162_rn(make_float2(v0.x, v0.y));
        __nv_bfloat162 p1 = __float22bfloat162_rn(make_float2(v0.z, v0.w));
        __nv_bfloat162 p2 = __float22bfloat162_rn(make_float2(v1.x, v1.y));
        __nv_bfloat162 p3 = __float22bfloat162_rn(make_float2(v1.z, v1.w));
        Au4[row*RSU4 + c] = make_uint4(*(const uint32_t*)&p0, *(const uint32_t*)&p1,
                                       *(const uint32_t*)&p2, *(const uint32_t*)&p3);
    }
    if (tid < 128) {
        bias[tid]       = b1[tid];
        bias[128 + tid] = b2[tid];
        bias[256 + tid] = b3[tid];
    }
    if (tid < 64) sq_sm[tid] = 0.0f;

    uint32_t waS = smem_to_u32(smc + MLP_WA);
    uint32_t wbS = smem_to_u32(smc + MLP_WB);

    // W1 -> WA (group 0), then W2 -> WB (group 1) prefetched
    wait_flag(&g_wdone[0]);
    for (int e = tid; e < 2048; e += 256)
        cp16(waS + (uint32_t)(e + (e >> 4))*16, (const char*)g_wt[0] + e*16);
    CP_COMMIT();
    wait_flag(&g_wdone[1]);
    for (int e = tid; e < 2048; e += 256)
        cp16(wbS + (uint32_t)(e + (e >> 4))*16, (const char*)g_wt[1] + e*16);
    CP_COMMIT();

    CP_WAIT(1);            // W1 complete (W2 may still fly)
    __syncthreads();       // + A stores visible

    float acc[2][4][4];

    // layer 1: A * WA -> B
    mlp_mma(smc, MLP_A, MLP_WA, acc, lane, wr, wc);
    mlp_store<true, false>(smc, MLP_B, acc, bias, lane, wr, wc);
    CP_WAIT(0);
    __syncthreads();       // L1 reads done; W2 ready; B visible

    // prefetch W3 -> WA (WA free now)
    wait_flag(&g_wdone[2]);
    for (int e = tid; e < 2048; e += 256)
        cp16(waS + (uint32_t)(e + (e >> 4))*16, (const char*)g_wt[2] + e*16);
    CP_COMMIT();

    // layer 2: B * WB -> A
    mlp_mma(smc, MLP_B, MLP_WB, acc, lane, wr, wc);
    mlp_store<true, false>(smc, MLP_A, acc, bias + 128, lane, wr, wc);
    CP_WAIT(0);
    __syncthreads();       // L2 reads done; W3 ready; A visible

    // layer 3: A * WA -> B (no relu), sq from rounded values
    mlp_mma(smc, MLP_A, MLP_WA, acc, lane, wr, wc);
    mlp_store<false, true>(smc, MLP_B, acc, bias + 256, lane, wr, wc);
    __syncthreads();

    // write h block: padded smem -> plain g_h rows
    for (int e = tid; e < 1024; e += 256) {
        int row = e >> 4;
        ((uint4*)g_h)[(r0 + row)*16 + (e & 15)] = ((uint4*)(smc + MLP_B))[e + row];
    }
    if (tid < 64) {
        float sv = sq_sm[tid];
        g_sq[r0 + tid] = sv;
        sv += __shfl_xor_sync(0xffffffffu, sv, 16);
        sv += __shfl_xor_sync(0xffffffffu, sv, 8);
        sv += __shfl_xor_sync(0xffffffffu, sv, 4);
        sv += __shfl_xor_sync(0xffffffffu, sv, 2);
        sv += __shfl_xor_sync(0xffffffffu, sv, 1);
        if (lane == 0) red[wid] = sv;
    }
    __syncthreads();
    if (tid == 0) atomicAdd(&g_hsum, (double)(red[0] + red[1]));
}

// ---------------------------------------------------------------------------
// Pairwise (R12/R15 exact): one 128x128 tile per CTA, 2080 CTAs, 3 CTAs/SM.
// smem: header 4KB | Hi(128r) | Hj(128r) = 73728 B
// Finalizer additionally resets ALL device state for the next graph replay.
// ---------------------------------------------------------------------------
#define HI_OFF 4096
#define HJ_OFF (4096 + TILE128)
#define PAIR_SMEM (4096 + 2*TILE128)

__global__ void __launch_bounds__(256, 3)
k_pair(const int* __restrict__ y, float* __restrict__ out) {
    extern __shared__ char smc[];
    float* redf = (float*)(smc + 16);
    float* sqi  = (float*)(smc + 64);
    float* sqj  = (float*)(smc + 576);
    int*   yi   = (int*)(smc + 1088);
    int*   yj   = (int*)(smc + 1600);

    int tid = threadIdx.x, wid = tid >> 5, lane = tid & 31;
    int wr = wid & 3, wc = wid >> 2;

    // triangular tile mapping: block t -> (bi, bj) with bi <= bj
    int t = blockIdx.x;
    float nf = (float)NT + 0.5f;
    int bi = (int)(nf - sqrtf(nf*nf - 2.0f*(float)t));
    if (bi < 0) bi = 0;
    if (bi >= NT) bi = NT - 1;
    while (bi*NT - (bi*(bi-1))/2 > t) bi--;
    while ((bi+1)*NT - ((bi+1)*bi)/2 <= t) bi++;
    int bj = bi + (t - (bi*NT - (bi*(bi-1))/2));

    // tile loads: plain g_h rows -> padded smem
    const uint4* gh = (const uint4*)g_h;
    uint4* Hi = (uint4*)(smc + HI_OFF);
    uint4* Hj = (uint4*)(smc + HJ_OFF);
    for (int e = tid; e < 2048; e += 256) {
        int pad = e >> 4;
        Hi[e + pad] = gh[bi*2048 + e];
        Hj[e + pad] = gh[bj*2048 + e];
    }
    if (tid < 128) {
        sqi[tid] = g_sq[bi*128 + tid];
        sqj[tid] = g_sq[bj*128 + tid];
        yi[tid]  = y[bi*128 + tid];
        yj[tid]  = y[bj*128 + tid];
    }
    __syncthreads();

    uint32_t hiB = smem_to_u32(smc + HI_OFF);
    uint32_t hjB = smem_to_u32(smc + HJ_OFF);

    int bg = lane >> 3;
    uint32_t aA0 = hiB + (uint32_t)(wr*32 + (lane & 15))*RS + (uint32_t)(lane >> 4)*16;
    uint32_t bBase = hjB + (uint32_t)(((bg >> 1) << 3) + (lane & 7))*RS
                   + (uint32_t)(bg & 1)*16;

    int r8 = lane >> 2, c2 = (lane & 3) << 1;
    float si[2][2]; int li[2][2];
    #pragma unroll
    for (int mt = 0; mt < 2; mt++)
        #pragma unroll
        for (int h = 0; h < 2; h++) {
            int row = wr*32 + mt*16 + h*8 + r8;
            si[mt][h] = sqi[row];
            li[mt][h] = yi[row];
        }

    float lsum = 0.0f;

    #pragma unroll 1
    for (int p = 0; p < 2; p++) {
        uint32_t bA0 = bBase + (uint32_t)(wc*64 + p*32)*RS;

        float acc[2][4][4];
        #pragma unroll
        for (int mt = 0; mt < 2; mt++)
            #pragma unroll
            for (int nt = 0; nt < 4; nt++)
                #pragma unroll
                for (int k = 0; k < 4; k++) acc[mt][nt][k] = 0.0f;

        #pragma unroll
        for (int ks = 0; ks < 8; ks++) {
            uint32_t a[2][4];
            ldm_x4(a[0][0], a[0][1], a[0][2], a[0][3], aA0 + ks*32);
            ldm_x4(a[1][0], a[1][1], a[1][2], a[1][3], aA0 + 16*RS + ks*32);
            uint32_t bfr[4][2];
            {
                uint32_t r0, r1, r2, r3;
                ldm_x4(r0, r1, r2, r3, bA0 + ks*32);
                bfr[0][0] = r0; bfr[0][1] = r1; bfr[1][0] = r2; bfr[1][1] = r3;
                ldm_x4(r0, r1, r2, r3, bA0 + 16*RS + ks*32);
                bfr[2][0] = r0; bfr[2][1] = r1; bfr[3][0] = r2; bfr[3][1] = r3;
            }
            #pragma unroll
            for (int mt = 0; mt < 2; mt++)
                #pragma unroll
                for (int nt = 0; nt < 4; nt++)
                    mma_bf16(acc[mt][nt], a[mt], bfr[nt]);
        }

        // epilogue for this half
        float sj[4][2]; int lj[4][2];
        #pragma unroll
        for (int nt = 0; nt < 4; nt++)
            #pragma unroll
            for (int q = 0; q < 2; q++) {
                int col = wc*64 + p*32 + nt*8 + c2 + q;
                sj[nt][q] = sqj[col];
                lj[nt][q] = yj[col];
            }

        int rare = 0;
        #pragma unroll
        for (int mt = 0; mt < 2; mt++)
            #pragma unroll
            for (int nt = 0; nt < 4; nt++)
                #pragma unroll
                for (int h = 0; h < 2; h++)
                    #pragma unroll
                    for (int q = 0; q < 2; q++) {
                        float d = acc[mt][nt][h*2 + q];
                        float dist = fmaf(-2.0f, d, si[mt][h] + sj[nt][q]);
                        bool  eq = (li[mt][h] == lj[nt][q]);
                        lsum += eq ? dist : FARV;
                        rare |= (!eq && dist < 18.0f);
                    }
        if (__any_sync(0xffffffffu, rare)) {
            #pragma unroll
            for (int mt = 0; mt < 2; mt++)
                #pragma unroll
                for (int nt = 0; nt < 4; nt++)
                    #pragma unroll
                    for (int h = 0; h < 2; h++)
                        #pragma unroll
                        for (int q = 0; q < 2; q++) {
                            float d = acc[mt][nt][h*2 + q];
                            float dist = fmaxf(fmaf(-2.0f, d, si[mt][h] + sj[nt][q]), 0.0f);
                            bool  eq = (li[mt][h] == lj[nt][q]);
                            if (!eq && dist < 18.0f)
                                lsum += (-logf(1.01f - expf(-dist))) - FARV;
                        }
        }
    }

    lsum += __shfl_xor_sync(0xffffffffu, lsum, 1);
    lsum += __shfl_xor_sync(0xffffffffu, lsum, 2);
    lsum += __shfl_xor_sync(0xffffffffu, lsum, 4);
    lsum += __shfl_xor_sync(0xffffffffu, lsum, 8);
    lsum += __shfl_xor_sync(0xffffffffu, lsum, 16);
    if (lane == 0) redf[wid] = lsum;
    __syncthreads();
    if (tid == 0) {
        double tot = 0.0;
        for (int w = 0; w < 8; w++) tot += (double)redf[w];
        if (bi != bj) tot *= 2.0;
        atomicAdd(&g_loss, tot);
        __threadfence();
        unsigned tk = atomicAdd(&g_ticket, 1u);
        if (tk == NBLK - 1) {
            __threadfence();
            double lt = atomicAdd(&g_loss, 0.0);
            double hs = atomicAdd(&g_hsum, 0.0);
            double loss = lt / ((double)BN * (double)BN);
            loss += 0.01 * (hs / ((double)BN * (double)DD));
            out[0] = (float)loss;
            // reset ALL device state for the next graph replay
            g_loss = 0.0; g_hsum = 0.0;
            g_wcnt[0] = 0u; g_wcnt[1] = 0u; g_wcnt[2] = 0u;
            g_wdone[0] = 0u; g_wdone[1] = 0u; g_wdone[2] = 0u;
            __threadfence();
            atomicExch(&g_ticket, 0u);
        }
    }
}

// ---------------------------------------------------------------------------

extern "C" void kernel_launch(void* const* d_in, const int* in_sizes, int n_in,
                              void* d_out, int out_size) {
    (void)in_sizes; (void)n_in; (void)out_size;
    const float* X  = (const float*)d_in[0];
    const float* W1 = (const float*)d_in[1];
    const float* b1 = (const float*)d_in[2];
    const float* W2 = (const float*)d_in[3];
    const float* b2 = (const float*)d_in[4];
    const float* W3 = (const float*)d_in[5];
    const float* b3 = (const float*)d_in[6];
    const int*   y  = (const int*)d_in[7];

    cudaFuncSetAttribute(k_mlp,  cudaFuncAttributeMaxDynamicSharedMemorySize, MLP_SMEM);
    cudaFuncSetAttribute(k_pair, cudaFuncAttributeMaxDynamicSharedMemorySize, PAIR_SMEM);

    k_mlp<<<BN/64, 256, MLP_SMEM>>>(X, W1, b1, W2, b2, W3, b3);
    k_pair<<<NBLK, 256, PAIR_SMEM>>>(y, (float*)d_out);
}